// round 10
// baseline (speedup 1.0000x reference)
#include <cuda_runtime.h>

#define NQ 4
#define NL 2

typedef unsigned long long u64;

// ---------------- packed f32x2 helpers (sm_103a) ----------------
__device__ __forceinline__ u64 pk2(float lo, float hi) {
    u64 r;
    asm("mov.b64 %0, {%1, %2};" : "=l"(r) : "f"(lo), "f"(hi));
    return r;
}
__device__ __forceinline__ void unpk2(u64 v, float& lo, float& hi) {
    asm("mov.b64 {%0, %1}, %2;" : "=f"(lo), "=f"(hi) : "l"(v));
}
__device__ __forceinline__ u64 mul2(u64 a, u64 b) {
    u64 r;
    asm("mul.rn.f32x2 %0, %1, %2;" : "=l"(r) : "l"(a), "l"(b));
    return r;
}
__device__ __forceinline__ u64 add2(u64 a, u64 b) {
    u64 r;
    asm("add.rn.f32x2 %0, %1, %2;" : "=l"(r) : "l"(a), "l"(b));
    return r;
}
__device__ __forceinline__ u64 fma2(u64 a, u64 b, u64 c) {
    u64 r;
    asm("fma.rn.f32x2 %0, %1, %2, %3;" : "=l"(r) : "l"(a), "l"(b), "l"(c));
    return r;
}

// Batch-invariant constants (both f32x2 lanes duplicated).
//  - Layer-0 RYs in tan form; scalar C'=prod cos(w0/2) folded as C'^2 into coeffs.
//  - Layer-1 RYs absorbed: RY(th)^T Z RY(th) = cos(th) Z - sin(th) X.
struct Consts {
    u64 tp[NQ];    // (+tan(w0_i/2))
    u64 tn[NQ];    // (-tan(w0_i/2))
    u64 h0[16];    // Z-part coeffs, head row 0
    u64 h1[16];    // Z-part coeffs, head row 1
    u64 v0[NQ];    // X-part coeffs, head row 0
    u64 v1[NQ];    // X-part coeffs, head row 1
    u64 b0, b1;
};

__device__ Consts g_scratch;          // written by setup_kernel
__constant__ Consts c_consts;         // filled via D2D memcpy; read via constant port

__global__ void setup_kernel(const float* __restrict__ weights,
                             const float* __restrict__ W,
                             const float* __restrict__ b) {
    if (threadIdx.x == 0 && blockIdx.x == 0) {
        float C = 1.0f;
        for (int i = 0; i < NQ; ++i) {
            float h = 0.5f * weights[i];          // layer 0
            float c = cosf(h), s = sinf(h);
            float t = s / c;
            C *= c;
            g_scratch.tp[i] = pk2(t, t);
            g_scratch.tn[i] = pk2(-t, -t);
        }
        float C2 = C * C;
        float c1[NQ], s1[NQ];
        for (int i = 0; i < NQ; ++i) {
            c1[i] = cosf(weights[NQ + i]);        // layer 1, full angle
            s1[i] = sinf(weights[NQ + i]);
        }
        for (int s = 0; s < 16; ++s) {
            float a0 = 0.0f, a1 = 0.0f;
            for (int i = 0; i < NQ; ++i) {
                float sign = ((s >> (3 - i)) & 1) ? -1.0f : 1.0f;
                a0 += W[0 * NQ + i] * c1[i] * sign;
                a1 += W[1 * NQ + i] * c1[i] * sign;
            }
            g_scratch.h0[s] = pk2(C2 * a0, C2 * a0);
            g_scratch.h1[s] = pk2(C2 * a1, C2 * a1);
        }
        for (int i = 0; i < NQ; ++i) {
            float u0 = -2.0f * C2 * W[0 * NQ + i] * s1[i];
            float u1 = -2.0f * C2 * W[1 * NQ + i] * s1[i];
            g_scratch.v0[i] = pk2(u0, u0);
            g_scratch.v1[i] = pk2(u1, u1);
        }
        g_scratch.b0 = pk2(b[0], b[0]);
        g_scratch.b1 = pk2(b[1], b[1]);
    }
}

// tan-form RY on qubit q: a0' = a0 - t*a1 ; a1' = a1 + t*a0
__device__ __forceinline__ void ry_tan(u64 a[16], int q, u64 tp, u64 tn) {
    const int m = 1 << (3 - q);
#pragma unroll
    for (int idx = 0; idx < 16; ++idx) {
        if (!(idx & m)) {
            u64 a0 = a[idx];
            u64 a1 = a[idx | m];
            a[idx]     = fma2(tn, a1, a0);
            a[idx | m] = fma2(tp, a0, a1);
        }
    }
}

// CNOT: compile-time register permutation (zero instructions after unroll).
__device__ __forceinline__ void cnot2(u64 a[16], int ctrl, int tgt) {
    const int mc = 1 << (3 - ctrl);
    const int mt = 1 << (3 - tgt);
#pragma unroll
    for (int s = 0; s < 16; ++s) {
        if ((s & mc) && !(s & mt)) {
            u64 tmp = a[s];
            a[s] = a[s | mt];
            a[s | mt] = tmp;
        }
    }
}

__global__ __launch_bounds__(128)
void sim_kernel(const float4* __restrict__ x, float4* __restrict__ out, int Bpair) {
    int t = blockIdx.x * blockDim.x + threadIdx.x;
    if (t >= Bpair) return;

    float4 xa = x[2 * t];
    float4 xb = x[2 * t + 1];

    float c0a, s0a, c1a, s1a, c2a, s2a, c3a, s3a;
    float c0b, s0b, c1b, s1b, c2b, s2b, c3b, s3b;
    __sincosf(0.5f * xa.x, &s0a, &c0a);
    __sincosf(0.5f * xa.y, &s1a, &c1a);
    __sincosf(0.5f * xa.z, &s2a, &c2a);
    __sincosf(0.5f * xa.w, &s3a, &c3a);
    __sincosf(0.5f * xb.x, &s0b, &c0b);
    __sincosf(0.5f * xb.y, &s1b, &c1b);
    __sincosf(0.5f * xb.z, &s2b, &c2b);
    __sincosf(0.5f * xb.w, &s3b, &c3b);

    u64 c0 = pk2(c0a, c0b), s0 = pk2(s0a, s0b);
    u64 c1 = pk2(c1a, c1b), s1 = pk2(s1a, s1b);
    u64 c2 = pk2(c2a, c2b), s2 = pk2(s2a, s2b);
    u64 c3 = pk2(c3a, c3b), s3 = pk2(s3a, s3b);

    // Product state via balanced pair tree (24 muls, depth 2 after MUFU).
    u64 t01[4], t23[4];
    t01[0] = mul2(c0, c1);  t01[1] = mul2(c0, s1);
    t01[2] = mul2(s0, c1);  t01[3] = mul2(s0, s1);
    t23[0] = mul2(c2, c3);  t23[1] = mul2(c2, s3);
    t23[2] = mul2(s2, c3);  t23[3] = mul2(s2, s3);

    u64 a[16];
#pragma unroll
    for (int s = 0; s < 16; ++s) {
        a[s] = mul2(t01[s >> 2], t23[s & 3]);
    }

    // Layer 0: CNOT ring (free) + tan-form RYs.
    cnot2(a, 0, 1);
    cnot2(a, 1, 2);
    cnot2(a, 2, 3);
    cnot2(a, 3, 0);
#pragma unroll
    for (int q = 0; q < NQ; ++q) {
        ry_tan(a, q, c_consts.tp[q], c_consts.tn[q]);
    }

    // Layer 1: CNOT ring (free); RYs absorbed into the measurement below.
    cnot2(a, 0, 1);
    cnot2(a, 1, 2);
    cnot2(a, 2, 3);
    cnot2(a, 3, 0);

    // Measurement: o_j = b_j + sum_s h_j[s] a_s^2 + sum_i v_j[i] y_i.
    // Accumulators split 2-way (even/odd s) to halve dependent-chain depth.
    u64 acc0e = c_consts.b0;
    u64 acc1e = c_consts.b1;
    u64 acc0o = mul2(mul2(a[1], a[1]), c_consts.h0[1]);
    u64 acc1o = mul2(mul2(a[1], a[1]), c_consts.h1[1]);
#pragma unroll
    for (int s = 0; s < 16; s += 2) {
        u64 p = mul2(a[s], a[s]);
        acc0e = fma2(c_consts.h0[s], p, acc0e);
        acc1e = fma2(c_consts.h1[s], p, acc1e);
    }
#pragma unroll
    for (int s = 3; s < 16; s += 2) {
        u64 p = mul2(a[s], a[s]);
        acc0o = fma2(c_consts.h0[s], p, acc0o);
        acc1o = fma2(c_consts.h1[s], p, acc1o);
    }

    // Cross terms y_i = sum over pairs a_s a_{s^m}, split 4+4.
#pragma unroll
    for (int i = 0; i < NQ; ++i) {
        const int m = 8 >> i;
        u64 ya, yb;
        int cnt = 0;
#pragma unroll
        for (int s = 0; s < 16; ++s) {
            if (!(s & m)) {
                u64 prod_src0 = a[s], prod_src1 = a[s | m];
                if (cnt == 0)      ya = mul2(prod_src0, prod_src1);
                else if (cnt == 1) yb = mul2(prod_src0, prod_src1);
                else if (cnt & 1)  yb = fma2(prod_src0, prod_src1, yb);
                else               ya = fma2(prod_src0, prod_src1, ya);
                ++cnt;
            }
        }
        u64 y = add2(ya, yb);
        if (i & 1) {
            acc0o = fma2(c_consts.v0[i], y, acc0o);
            acc1o = fma2(c_consts.v1[i], y, acc1o);
        } else {
            acc0e = fma2(c_consts.v0[i], y, acc0e);
            acc1e = fma2(c_consts.v1[i], y, acc1e);
        }
    }

    u64 acc0 = add2(acc0e, acc0o);
    u64 acc1 = add2(acc1e, acc1o);

    float o0a, o0b, o1a, o1b;
    unpk2(acc0, o0a, o0b);
    unpk2(acc1, o1a, o1b);

    out[t] = make_float4(o0a, o1a, o0b, o1b);
}

extern "C" void kernel_launch(void* const* d_in, const int* in_sizes, int n_in,
                              void* d_out, int out_size) {
    const float* x       = (const float*)d_in[0];  // (B, 4)
    const float* weights = (const float*)d_in[1];  // (2, 4)
    const float* W       = (const float*)d_in[2];  // (2, 4)
    const float* b       = (const float*)d_in[3];  // (2,)

    int B = in_sizes[0] / NQ;
    int Bpair = B / 2;

    setup_kernel<<<1, 32>>>(weights, W, b);

    void* dst = nullptr;
    void* src = nullptr;
    cudaGetSymbolAddress(&dst, c_consts);
    cudaGetSymbolAddress(&src, g_scratch);
    cudaMemcpyAsync(dst, src, sizeof(Consts), cudaMemcpyDeviceToDevice, 0);

    sim_kernel<<<(Bpair + 127) / 128, 128>>>((const float4*)x, (float4*)d_out, Bpair);
}